// round 5
// baseline (speedup 1.0000x reference)
#include <cuda_runtime.h>
#include <math.h>

// ---------------------------------------------------------------------------
// StericClashConstraint: out = [pos (N*3 floats), loss]
// loss = 0.02 * mean_{NxN}( max(1 - dist_ij, 0) ), diagonal masked.
// R5: node 1 = persistent zero+bin (one grid barrier).
//     node 2 = WARP-PER-CELL pair phase: neighbor counts loaded in one
//     parallel round, home points cached in smem, lanes stride coalesced
//     candidate slots of each 3-cell x-row; candidates loaded once per cell
//     (not once per point). Block reduce -> double atomic -> ticket write.
// Cell grid 32^3 over [-16,16): boundary clamp exact (cell >= 1, d2-tested).
// ---------------------------------------------------------------------------

#define GRID_DIM 32
#define NCELLS   (GRID_DIM * GRID_DIM * GRID_DIM)   // 32768
#define CAP      32
#define ORIGIN   (-16.0f)
#define CWEIGHT  0.02
#define NB       296
#define TPB      256

__device__ int    g_count[NCELLS];
__device__ float4 g_cellslot[NCELLS * CAP];          // 16 MB, L2-resident
__device__ double g_sum;
__device__ unsigned int g_done;

__device__ unsigned int g_bar_count = 0;
__device__ volatile unsigned int g_bar_gen = 0;      // monotone across replays

__device__ __forceinline__ int clampi(int v, int lo, int hi) {
    return v < lo ? lo : (v > hi ? hi : v);
}

__device__ __forceinline__ void grid_barrier() {
    __syncthreads();
    if (threadIdx.x == 0) {
        unsigned int gen = g_bar_gen;
        __threadfence();
        if (atomicAdd(&g_bar_count, 1u) == NB - 1) {
            g_bar_count = 0;
            __threadfence();
            g_bar_gen = gen + 1;
        } else {
            while (g_bar_gen == gen) __nanosleep(32);
        }
        __threadfence();
    }
    __syncthreads();
}

// -------- node 1: zero + bin (uniform persistent, one barrier) ----------
__global__ void __launch_bounds__(TPB, 2)
setup_kernel(const float* __restrict__ pos, float* __restrict__ out, int n) {
    const int tid = blockIdx.x * TPB + threadIdx.x;
    const int nth = NB * TPB;

    for (int c = tid; c < NCELLS; c += nth) g_count[c] = 0;
    if (tid == 0) { g_sum = 0.0; g_done = 0u; }
    grid_barrier();

    for (int i = tid; i < n; i += nth) {
        float x = pos[3 * i + 0];
        float y = pos[3 * i + 1];
        float z = pos[3 * i + 2];
        out[3 * i + 0] = x;
        out[3 * i + 1] = y;
        out[3 * i + 2] = z;
        int cx = clampi((int)floorf(x - ORIGIN), 0, GRID_DIM - 1);
        int cy = clampi((int)floorf(y - ORIGIN), 0, GRID_DIM - 1);
        int cz = clampi((int)floorf(z - ORIGIN), 0, GRID_DIM - 1);
        int c  = (cz * GRID_DIM + cy) * GRID_DIM + cx;
        int slot = atomicAdd(&g_count[c], 1);
        if (slot < CAP)
            g_cellslot[c * CAP + slot] = make_float4(x, y, z, __int_as_float(i));
    }
}

// -------- node 2: warp per cell --------
#define PB       256
#define WARPS_PB (PB / 32)
#define PAIR_BLOCKS (NCELLS / WARPS_PB)   // 4096

__global__ void __launch_bounds__(PB)
pair_kernel(float* __restrict__ out, int n) {
    __shared__ float4 s_home[WARPS_PB][CAP];
    const int lane = threadIdx.x & 31;
    const int wb   = threadIdx.x >> 5;
    const int cell = blockIdx.x * WARPS_PB + wb;

    float lsum = 0.0f;

    int cx = cell & 31;
    int cy = (cell >> 5) & 31;
    int cz = cell >> 10;

    // Parallel neighbor-count fetch: lane c in [0,27) owns neighbor cell c.
    int ncnt = 0, ncell = 0;
    if (lane < 27) {
        int gx = cx + (lane % 3) - 1;
        int gy = cy + ((lane / 3) % 3) - 1;
        int gz = cz + (lane / 9) - 1;
        if ((unsigned)gx < GRID_DIM && (unsigned)gy < GRID_DIM &&
            (unsigned)gz < GRID_DIM) {
            ncell = (gz * GRID_DIM + gy) * GRID_DIM + gx;
            ncnt  = g_count[ncell];
            ncnt  = ncnt < CAP ? ncnt : CAP;
        }
    }
    int m = __shfl_sync(0xFFFFFFFFu, ncnt, 13);   // home count (dz=dy=dx=0)

    if (m > 0) {
        if (lane < m) s_home[wb][lane] = g_cellslot[cell * CAP + lane];
        __syncwarp();

        #pragma unroll
        for (int r = 0; r < 9; r++) {
            int c0 = __shfl_sync(0xFFFFFFFFu, ncnt, r * 3 + 0);
            int c1 = __shfl_sync(0xFFFFFFFFu, ncnt, r * 3 + 1);
            int c2 = __shfl_sync(0xFFFFFFFFu, ncnt, r * 3 + 2);
            int b0 = __shfl_sync(0xFFFFFFFFu, ncell, r * 3 + 0);
            int b1 = __shfl_sync(0xFFFFFFFFu, ncell, r * 3 + 1);
            int b2 = __shfl_sync(0xFFFFFFFFu, ncell, r * 3 + 2);
            int c01 = c0 + c1;
            int total = c01 + c2;
            for (int t = lane; t < total; t += 32) {
                int ck, s;
                if (t < c0)       { ck = b0; s = t; }
                else if (t < c01) { ck = b1; s = t - c0; }
                else              { ck = b2; s = t - c01; }
                float4 q = g_cellslot[ck * CAP + s];
                int qi = __float_as_int(q.w);
                #pragma unroll 4
                for (int k = 0; k < m; k++) {
                    float4 p = s_home[wb][k];
                    float dx = p.x - q.x;
                    float dy = p.y - q.y;
                    float dz = p.z - q.z;
                    float d2 = fmaf(dx, dx, fmaf(dy, dy, dz * dz));
                    if (d2 < 1.0f && __float_as_int(p.w) != qi)
                        lsum += 1.0f - sqrtf(d2);
                }
            }
        }
    }

    // reduce: warp -> block -> double atomic -> ticket -> write loss
    __shared__ float s_warp[WARPS_PB];
    #pragma unroll
    for (int off = 16; off > 0; off >>= 1)
        lsum += __shfl_down_sync(0xFFFFFFFFu, lsum, off);
    if (lane == 0) s_warp[wb] = lsum;
    __syncthreads();
    if (wb == 0) {
        float v = (lane < WARPS_PB) ? s_warp[lane] : 0.0f;
        #pragma unroll
        for (int off = 4; off > 0; off >>= 1)
            v += __shfl_down_sync(0xFFFFFFFFu, v, off);
        if (lane == 0) {
            if (v != 0.0f) atomicAdd(&g_sum, (double)v);
            __threadfence();
            unsigned int prev = atomicAdd(&g_done, 1u);
            if (prev == (unsigned int)(PAIR_BLOCKS - 1)) {
                double nn = (double)n * (double)n;
                out[3 * n] = (float)(g_sum * (CWEIGHT / nn));
            }
        }
    }
}

extern "C" void kernel_launch(void* const* d_in, const int* in_sizes, int n_in,
                              void* d_out, int out_size) {
    const float* pos = (const float*)d_in[0];
    float* out = (float*)d_out;
    int n = in_sizes[0] / 3;   // 16384

    setup_kernel<<<NB, TPB>>>(pos, out, n);
    pair_kernel<<<PAIR_BLOCKS, PB>>>(out, n);
}